// round 9
// baseline (speedup 1.0000x reference)
#include <cuda_runtime.h>
#include <cuda_fp16.h>
#include <cstdint>

#define TOKENS 256
#define IN_F   4096
#define OUT_F  14336
#define KSPLIT 2
#define KPER   (IN_F / KSPLIT)   // 2048 K per CTA
#define NT     64                // N tile
#define KSTEP  32                // fp16 per smem stage
#define ITERS  (KPER / KSTEP)    // 64
#define THREADS 256
#define ROWB   80                // smem row pitch bytes (40 fp16, pad vs banks)
#define A_STAGE (256 * ROWB)     // 20480
#define B_STAGE (NT * ROWB)      // 5120
#define SMEM_TOTAL (2 * A_STAGE + 2 * B_STAGE)  // 51200

// scratch: x as fp16, per-token row sums, split-K fp32 partials
__device__ __align__(256) __half g_xh[TOKENS * IN_F];             // 2 MB
__device__ __align__(256) float  g_rowsum[KSPLIT][TOKENS];        // 1024·sum(x_h) per k-half
__device__ __align__(256) float  g_part[KSPLIT][TOKENS * OUT_F];  // 29 MB

// ---------------- helpers (generic PTX only: sm_80-era ops) ----------------
__device__ __forceinline__ uint32_t smem_u32(const void* p) {
    uint32_t a;
    asm("{ .reg .u64 t; cvta.to.shared.u64 t, %1; cvt.u32.u64 %0, t; }" : "=r"(a) : "l"(p));
    return a;
}
__device__ __forceinline__ void cp_async16(uint32_t dst, const void* src) {
    asm volatile("cp.async.cg.shared.global [%0], [%1], 16;" :: "r"(dst), "l"(src));
}
// pack low halfwords of two int32 weights, then bias to fp16 magic 1024+v
__device__ __forceinline__ uint32_t pack_magic(uint32_t a, uint32_t b) {
    uint32_t r;
    asm("prmt.b32 %0, %1, %2, 0x5410;" : "=r"(r) : "r"(a), "r"(b));
    return r | 0x64006400u;      // fp16 halves become (1024+v) exactly, v in [0,1023]
}
__device__ __forceinline__ void sts64(uint32_t addr, uint32_t lo, uint32_t hi) {
    asm volatile("st.shared.v2.u32 [%0], {%1, %2};" :: "r"(addr), "r"(lo), "r"(hi));
}
__device__ __forceinline__ void ldsm4(uint32_t* r, uint32_t addr) {
    asm volatile("ldmatrix.sync.aligned.m8n8.x4.shared.b16 {%0,%1,%2,%3}, [%4];"
                 : "=r"(r[0]), "=r"(r[1]), "=r"(r[2]), "=r"(r[3]) : "r"(addr));
}
__device__ __forceinline__ void mma16816(float* c, const uint32_t* a, const uint32_t* b) {
    asm volatile(
        "mma.sync.aligned.m16n8k16.row.col.f32.f16.f16.f32 "
        "{%0,%1,%2,%3}, {%4,%5,%6,%7}, {%8,%9}, {%0,%1,%2,%3};"
        : "+f"(c[0]), "+f"(c[1]), "+f"(c[2]), "+f"(c[3])
        : "r"(a[0]), "r"(a[1]), "r"(a[2]), "r"(a[3]), "r"(b[0]), "r"(b[1]));
}

// ---------------- kernels ----------------

// x f32 -> fp16 (plain, contiguous)
__global__ void prep_kernel(const float* __restrict__ x) {
    int i = blockIdx.x * blockDim.x + threadIdx.x;
    g_xh[i] = __float2half_rn(x[i]);
}

// per-token, per-k-half: g_rowsum = 1024 * sum(x_h)  (magic-bias correction)
__global__ void rowsum_kernel() {
    __shared__ float red[256];
    int t = blockIdx.x, ks = blockIdx.y;
    const __half* p = g_xh + (size_t)t * IN_F + ks * KPER;
    float s = 0.0f;
    for (int i = threadIdx.x; i < KPER; i += 256) s += __half2float(p[i]);
    red[threadIdx.x] = s;
    __syncthreads();
    for (int o = 128; o > 0; o >>= 1) {
        if (threadIdx.x < o) red[threadIdx.x] += red[threadIdx.x + o];
        __syncthreads();
    }
    if (threadIdx.x == 0) g_rowsum[ks][t] = red[0] * 1024.0f;
}

// grid (224, 2): blockIdx.x = N-tile (64 outs), blockIdx.y = K-half.
// A[256, 2048] fp16 x B[64, 2048] (fp16 = 1024+v, packed on the fly from int32 bytes)
__global__ void __launch_bounds__(THREADS, 2) gemm_kernel(const char* __restrict__ Wb) {
    extern __shared__ __align__(16) char smem[];
    uint32_t sb = smem_u32(smem);
    int tid = threadIdx.x, lane = tid & 31, wid = tid >> 5;
    int wm = wid >> 1, wn = wid & 1;              // 4 m-warps x 2 n-warps
    int n0 = blockIdx.x * NT;
    int k0 = blockIdx.y * KPER;                   // element offset in K

    const char* Wbase = Wb + (size_t)n0 * (IN_F * 4) + (size_t)k0 * 4;  // W row = 16384B
    const __half* Abase = g_xh + k0;

    // ldmatrix per-lane byte offsets within a stage
    uint32_t aoff[4], boff[2];
#pragma unroll
    for (int mt = 0; mt < 4; mt++)
        aoff[mt] = (uint32_t)((wm * 64 + mt * 16 + (lane & 15)) * ROWB + ((lane >> 4) << 4));
#pragma unroll
    for (int p = 0; p < 2; p++)
        boff[p] = (uint32_t)((wn * 32 + p * 16 + (lane & 7) + ((lane >> 4) << 3)) * ROWB
                             + (((lane >> 3) & 1) << 4));

    float acc[4][4][4];
#pragma unroll
    for (int mt = 0; mt < 4; mt++)
#pragma unroll
        for (int nt = 0; nt < 4; nt++)
#pragma unroll
            for (int q = 0; q < 4; q++) acc[mt][nt][q] = 0.0f;

    // producer indices
    int ar = tid >> 2, aq = tid & 3;              // A: rows ar+64c, 16B chunk aq
    int wr = tid >> 3, wq = tid & 7;              // W: rows wr+32j, 16B quad wq

    // --- producer lambdas ---
    auto issueA = [&](int it, int st) {
        uint32_t d = sb + st * A_STAGE + (uint32_t)(ar * ROWB + aq * 16);
        const char* s = (const char*)(Abase + (size_t)ar * IN_F + it * KSTEP + aq * 8);
#pragma unroll
        for (int c = 0; c < 4; c++)
            cp_async16(d + c * 64 * ROWB, s + (size_t)c * 64 * (IN_F * 2));
    };
    uint4 w0, w1;
    auto ldgW = [&](int it) {
        const char* s = Wbase + (size_t)wr * (IN_F * 4) + it * (KSTEP * 4) + wq * 16;
        w0 = *(const uint4*)s;
        w1 = *(const uint4*)(s + (size_t)32 * (IN_F * 4));
    };
    auto stsW = [&](int st) {
        uint32_t d = sb + 2 * A_STAGE + st * B_STAGE + (uint32_t)(wr * ROWB + wq * 8);
        sts64(d,              pack_magic(w0.x, w0.y), pack_magic(w0.z, w0.w));
        sts64(d + 32 * ROWB,  pack_magic(w1.x, w1.y), pack_magic(w1.z, w1.w));
    };

    // --- prologue: stage 0 ---
    issueA(0, 0);
    asm volatile("cp.async.commit_group;" ::: "memory");
    ldgW(0);
    stsW(0);
    asm volatile("cp.async.wait_group 0;" ::: "memory");
    __syncthreads();

    // --- main loop ---
#pragma unroll 1
    for (int it = 0; it < ITERS; ++it) {
        int st = it & 1, nst = st ^ 1;
        if (it + 1 < ITERS) {
            issueA(it + 1, nst);
            asm volatile("cp.async.commit_group;" ::: "memory");
            ldgW(it + 1);
        }
        // compute on stage st: 2 x k16 sub-steps
        uint32_t Ast = sb + st * A_STAGE;
        uint32_t Bst = sb + 2 * A_STAGE + st * B_STAGE;
#pragma unroll
        for (int ks = 0; ks < 2; ks++) {
            uint32_t a[4][4], b[2][4];
#pragma unroll
            for (int mt = 0; mt < 4; mt++) ldsm4(a[mt], Ast + aoff[mt] + ks * 32);
#pragma unroll
            for (int p = 0; p < 2; p++)    ldsm4(b[p], Bst + boff[p] + ks * 32);
#pragma unroll
            for (int mt = 0; mt < 4; mt++)
#pragma unroll
                for (int nt = 0; nt < 4; nt++)
                    mma16816(acc[mt][nt], a[mt], &b[nt >> 1][(nt & 1) * 2]);
        }
        if (it + 1 < ITERS) stsW(nst);
        asm volatile("cp.async.wait_group 0;" ::: "memory");
        __syncthreads();
    }

    // --- epilogue: raw fp32 partials (scale + magic correction in reduce) ---
    float* pb = g_part[blockIdx.y];
#pragma unroll
    for (int mt = 0; mt < 4; mt++) {
#pragma unroll
        for (int nt = 0; nt < 4; nt++) {
            int r0 = wm * 64 + mt * 16 + (lane >> 2);
            int col = n0 + wn * 32 + nt * 8 + (lane & 3) * 2;
            float2 v0 = make_float2(acc[mt][nt][0], acc[mt][nt][1]);
            float2 v1 = make_float2(acc[mt][nt][2], acc[mt][nt][3]);
            *(float2*)(pb + (size_t)r0 * OUT_F + col) = v0;
            *(float2*)(pb + (size_t)(r0 + 8) * OUT_F + col) = v1;
        }
    }
}

// out = (p0 + p1 - 1024*rowsum(x_h)) * scale + bias
__global__ void reduce_kernel(const float* __restrict__ scale,
                              const float* __restrict__ bias,
                              float* __restrict__ out) {
    int i = blockIdx.x * blockDim.x + threadIdx.x;   // float4 index
    int n4 = i % (OUT_F / 4);
    int t  = i / (OUT_F / 4);
    float corr = g_rowsum[0][t] + g_rowsum[1][t];
    float4 p0 = reinterpret_cast<const float4*>(g_part[0])[i];
    float4 p1 = reinterpret_cast<const float4*>(g_part[1])[i];
    float4 sc = reinterpret_cast<const float4*>(scale)[n4];
    float4 bi = reinterpret_cast<const float4*>(bias)[n4];
    float4 o;
    o.x = (p0.x + p1.x - corr) * sc.x + bi.x;
    o.y = (p0.y + p1.y - corr) * sc.y + bi.y;
    o.z = (p0.z + p1.z - corr) * sc.z + bi.z;
    o.w = (p0.w + p1.w - corr) * sc.w + bi.w;
    reinterpret_cast<float4*>(out)[i] = o;
}

extern "C" void kernel_launch(void* const* d_in, const int* in_sizes, int n_in,
                              void* d_out, int out_size) {
    const float* x     = (const float*)d_in[0];
    const char*  qw    = (const char*)d_in[1];   // int32 weights, byte view
    const float* scale = (const float*)d_in[2];
    const float* bias  = (const float*)d_in[3];
    float* out = (float*)d_out;

    cudaFuncSetAttribute(gemm_kernel, cudaFuncAttributeMaxDynamicSharedMemorySize, SMEM_TOTAL);

    prep_kernel<<<(TOKENS * IN_F) / 256, 256>>>(x);
    rowsum_kernel<<<dim3(TOKENS, KSPLIT), 256>>>();
    gemm_kernel<<<dim3(OUT_F / NT, KSPLIT), THREADS, SMEM_TOTAL>>>(qw);
    reduce_kernel<<<(TOKENS * OUT_F / 4) / 256, 256>>>(scale, bias, out);
}